// round 7
// baseline (speedup 1.0000x reference)
#include <cuda_runtime.h>
#include <cstdint>

// ---------------- problem constants ----------------
#define M_TOTAL 32768          // B*L tokens
#define K_DIM   1536           // H2
#define T_DIM   64             // tags
#define BM      256            // tokens per CTA
#define BK      32             // K per tile
#define NTK     (K_DIM / BK)   // 48 k-tiles
#define GRID    (M_TOTAL / BM) // 128 CTAs (1 per SM, single wave)
#define THREADS 256            // 8 warps: 4 (m) x 2 (n), warp tile 64m x 32n

// ---------------- dynamic SMEM layout (bytes) ----------------
#define SM_REDF   128                    // 8 floats
#define SM_REDR   192                    // 8 ints
#define SM_REDV   256                    // 8 ints
#define SM_LAST   448                    // int flag
#define SM_BIAS   512                    // 64 floats
#define A_ROW     80
#define A_BUF     (BM * A_ROW)           // 20480
#define W_BUF     (T_DIM * A_ROW)        // 5120
#define A_HI_OFF  1024
#define A_LO_OFF  (A_HI_OFF + 2 * A_BUF) // 41984
#define W_HI_OFF  (A_LO_OFF + 2 * A_BUF) // 82944
#define W_LO_OFF  (W_HI_OFF + 2 * W_BUF) // 93184
#define SMEM_TOTAL (W_LO_OFF + 2 * W_BUF) // 103424
// C overlay (after GEMM): [256][65] f32 at offset 1024 = 66560 bytes (fits)

// ---------------- device scratch (no allocs allowed) ----------------
__device__ float    g_part_loss[GRID];
__device__ int      g_part_right[GRID];
__device__ int      g_part_valid[GRID];
__device__ int      g_tag_stride;
__device__ unsigned g_done;              // zero-init; last CTA resets to 0 each run
__device__ unsigned g_whi[NTK * 1024];   // W bf16 hi tiles, [kt][n=64][k=32] (uint = 2 bf16)
__device__ unsigned g_wlo[NTK * 1024];   // W bf16 lo tiles

// ---------------- helpers ----------------
__device__ __forceinline__ uint32_t smem_u32(const void* p) {
    uint32_t a;
    asm("{ .reg .u64 t; cvta.to.shared.u64 t, %1; cvt.u32.u64 %0, t; }" : "=r"(a) : "l"(p));
    return a;
}
__device__ __forceinline__ unsigned cvt_bf16x2(float a, float b) {
    // result: lo16 = bf16(a), hi16 = bf16(b)
    unsigned r;
    asm("cvt.rn.bf16x2.f32 %0, %1, %2;" : "=r"(r) : "f"(b), "f"(a));
    return r;
}
__device__ __forceinline__ float lo_f32(unsigned w) { return __uint_as_float(w << 16); }
__device__ __forceinline__ float hi_f32(unsigned w) { return __uint_as_float(w & 0xffff0000u); }

#define LDMX4(r, addr)                                                          \
    asm volatile("ldmatrix.sync.aligned.m8n8.x4.shared.b16 {%0,%1,%2,%3}, [%4];"\
                 : "=r"((r)[0]), "=r"((r)[1]), "=r"((r)[2]), "=r"((r)[3])       \
                 : "r"(addr))

#define MMA16816(c, a, b0, b1)                                                  \
    asm volatile("mma.sync.aligned.m16n8k16.row.col.f32.bf16.bf16.f32 "         \
                 "{%0,%1,%2,%3}, {%4,%5,%6,%7}, {%8,%9}, {%0,%1,%2,%3};"        \
                 : "+f"((c)[0]), "+f"((c)[1]), "+f"((c)[2]), "+f"((c)[3])       \
                 : "r"((a)[0]), "r"((a)[1]), "r"((a)[2]), "r"((a)[3]),          \
                   "r"(b0), "r"(b1))

// ---------------- prep: W -> bf16 hi/lo tiles + tag dtype detection ----------------
__global__ void prep_kernel(const float* __restrict__ W,
                            const int* __restrict__ tagw) {
    if (blockIdx.x == 0 && threadIdx.x < 32) {
        int l = threadIdx.x;
        int nz = 0;
#pragma unroll
        for (int i = 0; i < 4; i++) nz |= tagw[2 * (l + 32 * i) + 1];
        unsigned ball = __ballot_sync(0xffffffffu, nz != 0);
        if (l == 0) g_tag_stride = ball ? 1 : 2;
    }

    const int kt  = blockIdx.x;
    const int t   = threadIdx.x;      // 256 threads
    const int n   = t >> 2;
    const int j0  = (t & 3) * 4;      // uint index within row (uint = 2 bf16 along k)
#pragma unroll
    for (int jj = 0; jj < 4; jj++) {
        int j = j0 + jj;
        float v0 = W[(size_t)(kt * BK + 2 * j)     * T_DIM + n];
        float v1 = W[(size_t)(kt * BK + 2 * j + 1) * T_DIM + n];
        unsigned h = cvt_bf16x2(v0, v1);
        float r0 = v0 - lo_f32(h);
        float r1 = v1 - hi_f32(h);
        unsigned l = cvt_bf16x2(r0, r1);
        g_whi[kt * 1024 + n * 16 + j] = h;
        g_wlo[kt * 1024 + n * 16 + j] = l;
    }
}

// ---------------- fused GEMM (mma.sync bf16 3-term split) + loss + finalize ----------------
__global__ __launch_bounds__(THREADS, 1)
void fused_gemm_loss_kernel(const float* __restrict__ x,
                            const float* __restrict__ bias,
                            const int*   __restrict__ tagw,
                            const float* __restrict__ tts,
                            const int*   __restrict__ tptr,
                            float* __restrict__ out)
{
    extern __shared__ char smem[];
    const uint32_t sb  = smem_u32(smem);
    const int tid  = threadIdx.x;
    const int wid  = tid >> 5;
    const int lane = tid & 31;
    const int wm   = wid >> 1;        // 0..3 (m group of 64 rows)
    const int wn   = wid & 1;         // 0..1 (n group of 32 cols)
    const int m0   = blockIdx.x * BM;

    if (tid < T_DIM) ((float*)(smem + SM_BIAS))[tid] = bias[tid];

    float c[4][4][4];                 // [i: m16 subtile][j: n8 subtile][frag]
#pragma unroll
    for (int i = 0; i < 4; i++)
#pragma unroll
        for (int j = 0; j < 4; j++)
#pragma unroll
            for (int q = 0; q < 4; q++) c[i][j][q] = 0.0f;

    // ---- prefetch tile 0 ----
    // x tile: 256 rows x 32 floats = 2048 float4; 256 threads -> 8 each
    // W tile: 512 uint2; 256 threads -> 2 each
    float4 xv[8]; uint2 whv[2], wlv[2];
    {
#pragma unroll
        for (int i = 0; i < 8; i++) {
            int lin = i * THREADS + tid;
            int row = lin >> 3, c4 = lin & 7;
            xv[i] = *(const float4*)(x + (size_t)(m0 + row) * K_DIM + c4 * 4);
        }
        whv[0] = ((const uint2*)g_whi)[tid];
        whv[1] = ((const uint2*)g_whi)[tid + 256];
        wlv[0] = ((const uint2*)g_wlo)[tid];
        wlv[1] = ((const uint2*)g_wlo)[tid + 256];
    }

    auto store_tile = [&](int b, const float4 xr[8], const uint2 wh[2], const uint2 wl[2]) {
        char* ah = smem + A_HI_OFF + b * A_BUF;
        char* al = smem + A_LO_OFF + b * A_BUF;
#pragma unroll
        for (int i = 0; i < 8; i++) {
            int lin = i * THREADS + tid;
            int row = lin >> 3, c4 = lin & 7;
            float4 f = xr[i];
            unsigned h01 = cvt_bf16x2(f.x, f.y);
            unsigned h23 = cvt_bf16x2(f.z, f.w);
            float r0 = f.x - lo_f32(h01), r1 = f.y - hi_f32(h01);
            float r2 = f.z - lo_f32(h23), r3 = f.w - hi_f32(h23);
            unsigned l01 = cvt_bf16x2(r0, r1);
            unsigned l23 = cvt_bf16x2(r2, r3);
            *(uint2*)(ah + row * A_ROW + c4 * 8) = make_uint2(h01, h23);
            *(uint2*)(al + row * A_ROW + c4 * 8) = make_uint2(l01, l23);
        }
#pragma unroll
        for (int i = 0; i < 2; i++) {
            int idx = i * THREADS + tid;
            int n = idx >> 3, j2 = (idx & 7) * 8;  // uint2 = 8 bytes
            *(uint2*)(smem + W_HI_OFF + b * W_BUF + n * A_ROW + j2) = wh[i];
            *(uint2*)(smem + W_LO_OFF + b * W_BUF + n * A_ROW + j2) = wl[i];
        }
    };

    store_tile(0, xv, whv, wlv);
    __syncthreads();

    const int quad = lane >> 3, r8 = lane & 7;

    for (int kt = 0; kt < NTK; kt++) {
        const int b = kt & 1;

        // prefetch next tile (LDG early, hidden under MMA)
        if (kt + 1 < NTK) {
            const int k0 = (kt + 1) * BK;
#pragma unroll
            for (int i = 0; i < 8; i++) {
                int lin = i * THREADS + tid;
                int row = lin >> 3, c4 = lin & 7;
                xv[i] = *(const float4*)(x + (size_t)(m0 + row) * K_DIM + k0 + c4 * 4);
            }
            whv[0] = ((const uint2*)g_whi)[(kt + 1) * 512 + tid];
            whv[1] = ((const uint2*)g_whi)[(kt + 1) * 512 + tid + 256];
            wlv[0] = ((const uint2*)g_wlo)[(kt + 1) * 512 + tid];
            wlv[1] = ((const uint2*)g_wlo)[(kt + 1) * 512 + tid + 256];
        }

        // ---- compute on buffer b ----
        const uint32_t aH = sb + A_HI_OFF + b * A_BUF;
        const uint32_t aL = sb + A_LO_OFF + b * A_BUF;
        const uint32_t wH = sb + W_HI_OFF + b * W_BUF;
        const uint32_t wL = sb + W_LO_OFF + b * W_BUF;

#pragma unroll
        for (int kk = 0; kk < 2; kk++) {
            // B fragments: n32 x k16 per precision (shared across 4 i subtiles)
            unsigned bh[8], bl[8];
            const int nB = wn * 32 + ((quad >> 1) << 3) + r8;
            const int kB = kk * 16 + ((quad & 1) << 3);
#pragma unroll
            for (int s = 0; s < 2; s++) {
                uint32_t off = (uint32_t)(nB + s * 16) * A_ROW + kB * 2;
                LDMX4(&bh[s * 4], wH + off);
                LDMX4(&bl[s * 4], wL + off);
            }
            const int kA = kk * 16 + ((quad >> 1) << 3);
#pragma unroll
            for (int i = 0; i < 4; i++) {
                unsigned ah[4], al[4];
                const int mA = wm * 64 + i * 16 + ((quad & 1) << 3) + r8;
                uint32_t off = (uint32_t)mA * A_ROW + kA * 2;
                LDMX4(ah, aH + off);
                LDMX4(al, aL + off);
#pragma unroll
                for (int j = 0; j < 4; j++) {
                    MMA16816(c[i][j], ah, bh[2 * j], bh[2 * j + 1]);
                    MMA16816(c[i][j], ah, bl[2 * j], bl[2 * j + 1]);
                    MMA16816(c[i][j], al, bh[2 * j], bh[2 * j + 1]);
                }
            }
        }

        if (kt + 1 < NTK) store_tile(b ^ 1, xv, whv, wlv);
        __syncthreads();
    }

    // ---- write C fragments to smem [256][65] f32 ----
    float* cs = (float*)(smem + A_HI_OFF);
    const int g = lane >> 2, tg = lane & 3;
#pragma unroll
    for (int i = 0; i < 4; i++)
#pragma unroll
        for (int j = 0; j < 4; j++) {
            int row = wm * 64 + i * 16 + g;
            int col = wn * 32 + j * 8 + tg * 2;
            cs[row * 65 + col]           = c[i][j][0];
            cs[row * 65 + col + 1]       = c[i][j][1];
            cs[(row + 8) * 65 + col]     = c[i][j][2];
            cs[(row + 8) * 65 + col + 1] = c[i][j][3];
        }
    __syncthreads();

    // ---- per-token loss/acc (one token per thread) ----
    const float* biass = (const float*)(smem + SM_BIAS);
    float thr_loss = 0.0f; int thr_right = 0, thr_valid = 0;
    {
        const int token = m0 + tid;
        const int tag = (g_tag_stride == 2) ? tagw[2 * token] : tagw[token];
        const float* row = cs + tid * 65;

        float mv = -3.4e38f; int mi = 0;
        float sl = 0.0f, st = 0.0f;
#pragma unroll
        for (int cc = 0; cc < T_DIM; cc++) {
            float vv = row[cc] + biass[cc];
            sl += vv;
            if (vv > mv) { mv = vv; mi = cc; }
            if (cc == tag) st = vv;
        }
        float se = 0.0f;
#pragma unroll
        for (int cc = 0; cc < T_DIM; cc++)
            se += expf(row[cc] + biass[cc] - mv);

        const float E1 = 2.718281828459045f;
        float LSE = mv + logf(se);
        int   traw = *tptr;
        float tf = (traw > -1000000 && traw < 1000000) ? (float)traw : __int_as_float(traw);
        float s  = powf(tts[tag], tf);
        float es = expf(s);
        float Z  = 63.0f * E1 + es;
        thr_loss  = LSE - ((E1 / Z) * (sl - st) + (es / Z) * st);
        thr_valid = (tag < (T_DIM - 3)) ? 1 : 0;
        thr_right = (thr_valid && (mi == tag)) ? 1 : 0;
    }

    // ---- deterministic block reduction (8 warps) ----
    float* s_loss  = (float*)(smem + SM_REDF);
    int*   s_right = (int*)(smem + SM_REDR);
    int*   s_valid = (int*)(smem + SM_REDV);
    int*   s_last  = (int*)(smem + SM_LAST);
#pragma unroll
    for (int off = 16; off > 0; off >>= 1) {
        thr_loss  += __shfl_xor_sync(0xffffffffu, thr_loss,  off);
        thr_right += __shfl_xor_sync(0xffffffffu, thr_right, off);
        thr_valid += __shfl_xor_sync(0xffffffffu, thr_valid, off);
    }
    if (lane == 0) { s_loss[wid] = thr_loss; s_right[wid] = thr_right; s_valid[wid] = thr_valid; }
    __syncthreads();
    if (tid == 0) {
        float L = 0.0f; int R = 0, V = 0;
        for (int w = 0; w < 8; w++) { L += s_loss[w]; R += s_right[w]; V += s_valid[w]; }
        g_part_loss[blockIdx.x]  = L;
        g_part_right[blockIdx.x] = R;
        g_part_valid[blockIdx.x] = V;
        __threadfence();
        unsigned prev = atomicAdd(&g_done, 1u);
        *s_last = (prev == GRID - 1) ? 1 : 0;
    }
    __syncthreads();

    // ---- last CTA: deterministic global reduction + output ----
    if (*s_last) {
        __threadfence();   // acquire all partials
        float L = 0.0f; int R = 0, V = 0;
        if (tid < GRID) {  // GRID == 128 -> warps 0..3
            L = g_part_loss[tid];
            R = g_part_right[tid];
            V = g_part_valid[tid];
        }
#pragma unroll
        for (int off = 16; off > 0; off >>= 1) {
            L += __shfl_xor_sync(0xffffffffu, L, off);
            R += __shfl_xor_sync(0xffffffffu, R, off);
            V += __shfl_xor_sync(0xffffffffu, V, off);
        }
        if (lane == 0) { s_loss[wid] = L; s_right[wid] = R; s_valid[wid] = V; }
        __syncthreads();
        if (tid == 0) {
            double LT = 0.0; long long RT = 0, VT = 0;
            for (int w = 0; w < 4; w++) {
                LT += (double)s_loss[w]; RT += s_right[w]; VT += s_valid[w];
            }
            out[0] = (float)LT;
            out[1] = (float)((double)RT / (double)VT);
            atomicExch(&g_done, 0u);   // reset for next graph replay
        }
    }
}

extern "C" void kernel_launch(void* const* d_in, const int* in_sizes, int n_in,
                              void* d_out, int out_size) {
    const float* x    = (const float*)d_in[0];
    const float* W    = (const float*)d_in[1];
    const float* b    = (const float*)d_in[2];
    const int*   tagw = (const int*)d_in[3];   // raw 32-bit view, dtype detected on device
    // d_in[4] = attention_mask: uniform additive shift over tag dim -> provably a no-op
    const float* tts  = (const float*)d_in[5];
    const int*   tptr = (const int*)d_in[6];

    static int smem_set = 0;
    if (!smem_set) {
        cudaFuncSetAttribute(fused_gemm_loss_kernel,
                             cudaFuncAttributeMaxDynamicSharedMemorySize, SMEM_TOTAL);
        smem_set = 1;
    }

    prep_kernel<<<NTK, 256>>>(W, tagw);
    fused_gemm_loss_kernel<<<GRID, THREADS, SMEM_TOTAL>>>(x, b, tagw, tts, tptr,
                                                          (float*)d_out);
}